// round 3
// baseline (speedup 1.0000x reference)
#include <cuda_runtime.h>
#include <cstddef>

// Problem constants
#define NTOK 8192   // N
#define BB   32     // batch
#define GD   256    // GRU_DIM
#define HD   512    // HAN_DIM
#define ID   128    // INNER_DIM

typedef unsigned long long u64;

__device__ __forceinline__ u64 f2dup(float x) {
    u64 r; asm("mov.b64 %0, {%1, %1};" : "=l"(r) : "f"(x)); return r;
}
__device__ __forceinline__ u64 fma2(u64 a, u64 b, u64 c) {
    u64 d; asm("fma.rn.f32x2 %0, %1, %2, %3;" : "=l"(d) : "l"(a), "l"(b), "l"(c)); return d;
}
__device__ __forceinline__ float2 f2unpack(u64 v) {
    float2 r; asm("mov.b64 {%0, %1}, %2;" : "=f"(r.x), "=f"(r.y) : "l"(v)); return r;
}

// Scratch (device globals; no allocation)
__device__ float g_K[NTOK * ID];    // 4 MB
__device__ float g_M[NTOK * GD];    // 8 MB
__device__ float g_WkT[HD * ID];    // 256 KB: WkT[k][n] = Wk[n][k]

// ======================= Kernel P: transpose Wk [128,512] -> WkT [512,128] =======================
__global__ void transpose_wk_kernel(const float* __restrict__ Wk)
{
    __shared__ float s[32][33];
    const int bx = blockIdx.x;   // k-tile 0..15
    const int by = blockIdx.y;   // n-tile 0..3
    const int tx = threadIdx.x;  // 0..31
    const int ty = threadIdx.y;  // 0..7
#pragma unroll
    for (int j = 0; j < 32; j += 8)
        s[ty + j][tx] = Wk[(size_t)(by * 32 + ty + j) * HD + bx * 32 + tx];  // s[n][k]
    __syncthreads();
#pragma unroll
    for (int j = 0; j < 32; j += 8)
        g_WkT[(size_t)(bx * 32 + ty + j) * ID + by * 32 + tx] = s[tx][ty + j];
}

// ======================= Kernel A1: K[8192,128] = edges[8192,512] @ WkT =======================
// Block tile 64(m) x 128(n), 256 threads, thread tile 4m x 8n (4 col-pairs), KC=32, 16 iters.
__global__ __launch_bounds__(256)
void gemm_k_kernel(const float* __restrict__ edg)
{
    __shared__ u64   sA2[64][36];    // A values pre-duplicated {a,a}; stride 36 u64
    __shared__ float sB[32][132];    // B[kk][n], rows 16B-aligned (132*4=528)

    const int tid = threadIdx.x;
    const int tm  = tid >> 4;        // 0..15 -> rows 4tm..4tm+3
    const int tn  = tid & 15;        // 0..15 -> cols 8tn..8tn+7
    const int m0  = blockIdx.x * 64;

    u64 acc[4][4];
#pragma unroll
    for (int m = 0; m < 4; m++)
#pragma unroll
        for (int p = 0; p < 4; p++) acc[m][p] = 0ull;

    // reg staging
    float4 ra[2], rb[4];
    // prologue: load kc=0
#pragma unroll
    for (int i = 0; i < 2; i++) {
        int idx = tid + i * 256; int r = idx >> 3, k4 = idx & 7;
        ra[i] = *reinterpret_cast<const float4*>(edg + (size_t)(m0 + r) * HD + 4 * k4);
    }
#pragma unroll
    for (int i = 0; i < 4; i++) {
        int idx = tid + i * 256; int kk = idx >> 5, n4 = idx & 31;
        rb[i] = *reinterpret_cast<const float4*>(g_WkT + (size_t)kk * ID + 4 * n4);
    }

    for (int it = 0; it < 16; ++it) {
        // commit staged regs to smem
#pragma unroll
        for (int i = 0; i < 2; i++) {
            int idx = tid + i * 256; int r = idx >> 3, k4 = idx & 7;
            sA2[r][4 * k4 + 0] = f2dup(ra[i].x);
            sA2[r][4 * k4 + 1] = f2dup(ra[i].y);
            sA2[r][4 * k4 + 2] = f2dup(ra[i].z);
            sA2[r][4 * k4 + 3] = f2dup(ra[i].w);
        }
#pragma unroll
        for (int i = 0; i < 4; i++) {
            int idx = tid + i * 256; int kk = idx >> 5, n4 = idx & 31;
            *reinterpret_cast<float4*>(&sB[kk][4 * n4]) = rb[i];
        }
        __syncthreads();

        // prefetch next chunk into regs (overlaps compute)
        if (it < 15) {
            int kc2 = (it + 1) * 32;
#pragma unroll
            for (int i = 0; i < 2; i++) {
                int idx = tid + i * 256; int r = idx >> 3, k4 = idx & 7;
                ra[i] = *reinterpret_cast<const float4*>(edg + (size_t)(m0 + r) * HD + kc2 + 4 * k4);
            }
#pragma unroll
            for (int i = 0; i < 4; i++) {
                int idx = tid + i * 256; int kk = idx >> 5, n4 = idx & 31;
                rb[i] = *reinterpret_cast<const float4*>(g_WkT + (size_t)(kc2 + kk) * ID + 4 * n4);
            }
        }

        // compute
#pragma unroll
        for (int kk = 0; kk < 32; kk++) {
            u64 a0 = sA2[4 * tm + 0][kk];
            u64 a1 = sA2[4 * tm + 1][kk];
            u64 a2 = sA2[4 * tm + 2][kk];
            u64 a3 = sA2[4 * tm + 3][kk];
            ulonglong2 bl = *reinterpret_cast<const ulonglong2*>(&sB[kk][8 * tn]);
            ulonglong2 bh = *reinterpret_cast<const ulonglong2*>(&sB[kk][8 * tn + 4]);
            acc[0][0] = fma2(a0, bl.x, acc[0][0]); acc[0][1] = fma2(a0, bl.y, acc[0][1]);
            acc[0][2] = fma2(a0, bh.x, acc[0][2]); acc[0][3] = fma2(a0, bh.y, acc[0][3]);
            acc[1][0] = fma2(a1, bl.x, acc[1][0]); acc[1][1] = fma2(a1, bl.y, acc[1][1]);
            acc[1][2] = fma2(a1, bh.x, acc[1][2]); acc[1][3] = fma2(a1, bh.y, acc[1][3]);
            acc[2][0] = fma2(a2, bl.x, acc[2][0]); acc[2][1] = fma2(a2, bl.y, acc[2][1]);
            acc[2][2] = fma2(a2, bh.x, acc[2][2]); acc[2][3] = fma2(a2, bh.y, acc[2][3]);
            acc[3][0] = fma2(a3, bl.x, acc[3][0]); acc[3][1] = fma2(a3, bl.y, acc[3][1]);
            acc[3][2] = fma2(a3, bh.x, acc[3][2]); acc[3][3] = fma2(a3, bh.y, acc[3][3]);
        }
        __syncthreads();
    }

    // epilogue
#pragma unroll
    for (int m = 0; m < 4; m++)
#pragma unroll
        for (int p = 0; p < 4; p++) {
            float2 v = f2unpack(acc[m][p]);
            *reinterpret_cast<float2*>(g_K + (size_t)(m0 + 4 * tm + m) * ID + 8 * tn + 2 * p) = v;
        }
}

// ======================= Kernel A2: M[8192,256] = scale * (K @ Wq) =======================
// Block tile 64(m) x 256(n), 256 threads, thread tile 4m x 16n (8 pairs), KC=16, 8 iters.
__global__ __launch_bounds__(256)
void gemm_m_kernel(const float* __restrict__ Wq)
{
    __shared__ u64   sA2[64][18];
    __shared__ float sB[16][260];

    const int tid = threadIdx.x;
    const int tm  = tid >> 4;        // 0..15
    const int tn  = tid & 15;        // 0..15 -> cols 16tn..16tn+15
    const int m0  = blockIdx.x * 64;
    const float SCALE = 0.08838834764831845f;  // 128^-0.5

    u64 acc[4][8];
#pragma unroll
    for (int m = 0; m < 4; m++)
#pragma unroll
        for (int p = 0; p < 8; p++) acc[m][p] = 0ull;

    float4 ra, rb[4];
    // prologue ec=0
    {
        int r = tid >> 2, k4 = tid & 3;
        ra = *reinterpret_cast<const float4*>(g_K + (size_t)(m0 + r) * ID + 4 * k4);
#pragma unroll
        for (int i = 0; i < 4; i++) {
            int idx = tid + i * 256; int kk = idx >> 6, c4 = idx & 63;
            float4 v = *reinterpret_cast<const float4*>(Wq + (size_t)kk * GD + 4 * c4);
            v.x *= SCALE; v.y *= SCALE; v.z *= SCALE; v.w *= SCALE;
            rb[i] = v;
        }
    }

    for (int it = 0; it < 8; ++it) {
        {
            int r = tid >> 2, k4 = tid & 3;
            sA2[r][4 * k4 + 0] = f2dup(ra.x);
            sA2[r][4 * k4 + 1] = f2dup(ra.y);
            sA2[r][4 * k4 + 2] = f2dup(ra.z);
            sA2[r][4 * k4 + 3] = f2dup(ra.w);
        }
#pragma unroll
        for (int i = 0; i < 4; i++) {
            int idx = tid + i * 256; int kk = idx >> 6, c4 = idx & 63;
            *reinterpret_cast<float4*>(&sB[kk][4 * c4]) = rb[i];
        }
        __syncthreads();

        if (it < 7) {
            int ec2 = (it + 1) * 16;
            int r = tid >> 2, k4 = tid & 3;
            ra = *reinterpret_cast<const float4*>(g_K + (size_t)(m0 + r) * ID + ec2 + 4 * k4);
#pragma unroll
            for (int i = 0; i < 4; i++) {
                int idx = tid + i * 256; int kk = idx >> 6, c4 = idx & 63;
                float4 v = *reinterpret_cast<const float4*>(Wq + (size_t)(ec2 + kk) * GD + 4 * c4);
                v.x *= SCALE; v.y *= SCALE; v.z *= SCALE; v.w *= SCALE;
                rb[i] = v;
            }
        }

#pragma unroll
        for (int kk = 0; kk < 16; kk++) {
            u64 a0 = sA2[4 * tm + 0][kk];
            u64 a1 = sA2[4 * tm + 1][kk];
            u64 a2 = sA2[4 * tm + 2][kk];
            u64 a3 = sA2[4 * tm + 3][kk];
            ulonglong2 b0 = *reinterpret_cast<const ulonglong2*>(&sB[kk][16 * tn]);
            ulonglong2 b1 = *reinterpret_cast<const ulonglong2*>(&sB[kk][16 * tn + 4]);
            ulonglong2 b2 = *reinterpret_cast<const ulonglong2*>(&sB[kk][16 * tn + 8]);
            ulonglong2 b3 = *reinterpret_cast<const ulonglong2*>(&sB[kk][16 * tn + 12]);
#define A2_STEP(AM, M) \
            acc[M][0] = fma2(AM, b0.x, acc[M][0]); acc[M][1] = fma2(AM, b0.y, acc[M][1]); \
            acc[M][2] = fma2(AM, b1.x, acc[M][2]); acc[M][3] = fma2(AM, b1.y, acc[M][3]); \
            acc[M][4] = fma2(AM, b2.x, acc[M][4]); acc[M][5] = fma2(AM, b2.y, acc[M][5]); \
            acc[M][6] = fma2(AM, b3.x, acc[M][6]); acc[M][7] = fma2(AM, b3.y, acc[M][7]);
            A2_STEP(a0, 0) A2_STEP(a1, 1) A2_STEP(a2, 2) A2_STEP(a3, 3)
#undef A2_STEP
        }
        __syncthreads();
    }

#pragma unroll
    for (int m = 0; m < 4; m++)
#pragma unroll
        for (int p = 0; p < 8; p++) {
            float2 v = f2unpack(acc[m][p]);
            *reinterpret_cast<float2*>(g_M + (size_t)(m0 + 4 * tm + m) * GD + 16 * tn + 2 * p) = v;
        }
}

// ======================= Kernel B: sim + masked softmax over b =======================
#define JB2 8       // j-rows per block; grid = 1024

__global__ __launch_bounds__(256)
void cal_sim_stream_kernel(const float* __restrict__ chg,          // [B, N, GD]
                           const unsigned int* __restrict__ maskw, // [B, N] dtype probed
                           float* __restrict__ out)                // [N, B]
{
    __shared__ float s_M[JB2 * GD];
    __shared__ float s_sim[BB * 9];

    const int t    = threadIdx.x;
    const int lane = t & 31;
    const int warp = t >> 5;            // 0..7 == jr
    const int j0   = blockIdx.x * JB2;

#pragma unroll
    for (int i = 0; i < 2; i++) {
        int idx = t + i * 256;
        *reinterpret_cast<float4*>(s_M + 4 * idx) =
            *reinterpret_cast<const float4*>(g_M + (size_t)j0 * GD + 4 * idx);
    }
    __syncthreads();

    float4 m0 = reinterpret_cast<const float4*>(s_M + warp * GD)[2 * lane];
    float4 m1 = reinterpret_cast<const float4*>(s_M + warp * GD)[2 * lane + 1];

    const float* crow = chg + (size_t)(j0 + warp) * GD;

#pragma unroll 8
    for (int b = 0; b < BB; b++) {
        const float4* c = reinterpret_cast<const float4*>(crow + (size_t)b * NTOK * GD);
        float4 c0 = c[2 * lane];
        float4 c1 = c[2 * lane + 1];
        float part = c0.x * m0.x + c0.y * m0.y + c0.z * m0.z + c0.w * m0.w
                   + c1.x * m1.x + c1.y * m1.y + c1.z * m1.z + c1.w * m1.w;
#pragma unroll
        for (int s = 16; s; s >>= 1) part += __shfl_xor_sync(0xffffffffu, part, s);
        if (lane == 0) s_sim[b * 9 + warp] = part;
    }
    __syncthreads();

    // mask dtype probe
    bool notint = false, notfloat = false;
    for (int i = lane; i < 256; i += 32) {
        unsigned int w = maskw[i];
        notint   |= (w > 1u);
        notfloat |= (w != 0u && w != 0x3f800000u);
    }
    notint   = __any_sync(0xffffffffu, notint);
    notfloat = __any_sync(0xffffffffu, notfloat);
    const int mode = notint ? (notfloat ? 1 : 2) : 0;   // 0=int32, 1=byte, 2=float32

    {
        const int jg = j0 + warp;
        float v = s_sim[lane * 9 + warp];
        bool mk;
        if (mode == 0)      mk = reinterpret_cast<const int*>(maskw)[(size_t)lane * NTOK + jg] != 0;
        else if (mode == 1) mk = reinterpret_cast<const unsigned char*>(maskw)[(size_t)lane * NTOK + jg] != 0;
        else                mk = reinterpret_cast<const float*>(maskw)[(size_t)lane * NTOK + jg] != 0.0f;
        v = mk ? v : -1e9f;
        float mx = v;
#pragma unroll
        for (int s = 16; s; s >>= 1) mx = fmaxf(mx, __shfl_xor_sync(0xffffffffu, mx, s));
        float ev = expf(v - mx);
        float sum = ev;
#pragma unroll
        for (int s = 16; s; s >>= 1) sum += __shfl_xor_sync(0xffffffffu, sum, s);
        out[(size_t)jg * BB + lane] = ev / sum;
    }
}

extern "C" void kernel_launch(void* const* d_in, const int* in_sizes, int n_in,
                              void* d_out, int out_size)
{
    const float*        chg  = (const float*)d_in[0];        // change_embeddings [B,N,256]
    const float*        edg  = (const float*)d_in[1];        // edges_embeddings  [N,512]
    const unsigned int* mask = (const unsigned int*)d_in[2]; // mask [B,N]
    const float*        Wq   = (const float*)d_in[3];        // [128,256]
    const float*        Wk   = (const float*)d_in[4];        // [128,512]
    float*              out  = (float*)d_out;                // [N,B]

    transpose_wk_kernel<<<dim3(16, 4), dim3(32, 8)>>>(Wk);
    gemm_k_kernel<<<NTOK / 64, 256>>>(edg);
    gemm_m_kernel<<<NTOK / 64, 256>>>(Wq);
    cal_sim_stream_kernel<<<NTOK / JB2, 256>>>(chg, mask, out);
}

// round 5
// speedup vs baseline: 1.6982x; 1.6982x over previous
#include <cuda_runtime.h>
#include <cuda_bf16.h>
#include <cstddef>
#include <cstdint>

// Problem constants
#define NTOK 8192   // N
#define BB   32     // batch
#define GD   256    // GRU_DIM
#define HD   512    // HAN_DIM
#define ID   128    // INNER_DIM

// ---------------- device scratch (no allocation) ----------------
__device__ float         g_M[NTOK * GD];     // 8 MB: M[j,d]
__device__ __nv_bfloat16 g_Bhi[GD * HD];     // 256 KB: W2 hi [256][512] (k-contig)
__device__ __nv_bfloat16 g_Blo[GD * HD];     // 256 KB

__device__ __forceinline__ uint32_t smem_u32(const void* p) {
    uint32_t a;
    asm("{ .reg .u64 t; cvta.to.shared.u64 t, %1; cvt.u32.u64 %0, t; }" : "=r"(a) : "l"(p));
    return a;
}
__device__ __forceinline__ void ldsm4(uint32_t addr, uint32_t* r) {
    asm volatile("ldmatrix.sync.aligned.m8n8.x4.shared.b16 {%0,%1,%2,%3}, [%4];"
                 : "=r"(r[0]), "=r"(r[1]), "=r"(r[2]), "=r"(r[3]) : "r"(addr));
}
__device__ __forceinline__ void mma16816(float* c, const uint32_t* a, uint32_t b0, uint32_t b1) {
    asm volatile(
        "mma.sync.aligned.m16n8k16.row.col.f32.bf16.bf16.f32 "
        "{%0,%1,%2,%3}, {%4,%5,%6,%7}, {%8,%9}, {%0,%1,%2,%3};"
        : "+f"(c[0]), "+f"(c[1]), "+f"(c[2]), "+f"(c[3])
        : "r"(a[0]), "r"(a[1]), "r"(a[2]), "r"(a[3]), "r"(b0), "r"(b1));
}
__device__ __forceinline__ uint32_t pack_bf2(__nv_bfloat16 lo16, __nv_bfloat16 hi16) {
    __nv_bfloat162 t; t.x = lo16; t.y = hi16;
    return *reinterpret_cast<uint32_t*>(&t);
}

// ======================= P1: W2 = scale * Wq^T @ Wk, split to bf16 hi/lo =======================
__global__ __launch_bounds__(256)
void prep_w2_kernel(const float* __restrict__ Wq, const float* __restrict__ Wk)
{
    __shared__ float sq[32][33];   // [e][d]
    __shared__ float sk[32][65];   // [e][h]
    const int t  = threadIdx.x;
    const int d0 = blockIdx.x * 32;
    const int h0 = blockIdx.y * 64;
    const int td = t & 31;         // d
    const int th = t >> 5;         // h group (8 per thread)

    float acc[8] = {0, 0, 0, 0, 0, 0, 0, 0};
    for (int e0 = 0; e0 < ID; e0 += 32) {
#pragma unroll
        for (int i = 0; i < 4; i++) {
            int idx = t + i * 256; int e = idx >> 5, d = idx & 31;
            sq[e][d] = Wq[(size_t)(e0 + e) * GD + d0 + d];
        }
#pragma unroll
        for (int i = 0; i < 8; i++) {
            int idx = t + i * 256; int e = idx >> 6, h = idx & 63;
            sk[e][h] = Wk[(size_t)(e0 + e) * HD + h0 + h];
        }
        __syncthreads();
#pragma unroll
        for (int e = 0; e < 32; e++) {
            float q = sq[e][td];
#pragma unroll
            for (int i = 0; i < 8; i++) acc[i] += q * sk[e][th * 8 + i];
        }
        __syncthreads();
    }
    const float SCALE = 0.08838834764831845f;  // 128^-0.5
#pragma unroll
    for (int i = 0; i < 8; i++) {
        float v = acc[i] * SCALE;
        __nv_bfloat16 hi = __float2bfloat16(v);
        __nv_bfloat16 lo = __float2bfloat16(v - __bfloat162float(hi));
        size_t off = (size_t)(d0 + td) * HD + h0 + th * 8 + i;
        g_Bhi[off] = hi;
        g_Blo[off] = lo;
    }
}

// ======================= A: M[8192,256] = edges @ W2^T via mma.sync bf16 split =================
// 128 CTAs, block tile 64(M)x256(N), 8 warps (2m x 4n), warp tile 32x64, K-chunks of 64.
// smem rows padded to 144 B -> ldmatrix phases conflict-free (row starts 4r mod 32 banks).
#define ROWB   144                       // bytes per smem row (64 bf16 used + pad)
#define SA_H   0
#define SA_L   (SA_H + 64 * ROWB)        // 9216
#define SB_H   (SA_L + 64 * ROWB)        // 18432
#define SB_L   (SB_H + 256 * ROWB)       // 55296
#define GEMM_SMEM (SB_L + 256 * ROWB)    // 92160 B

__global__ __launch_bounds__(256)
void gemm_mma_kernel(const float* __restrict__ edg)   // [N, HD] fp32
{
    extern __shared__ char smem[];
    const uint32_t sbase = smem_u32(smem);
    uint32_t* sw = reinterpret_cast<uint32_t*>(smem);

    const int tid  = threadIdx.x;
    const int lane = tid & 31;
    const int wid  = tid >> 5;
    const int wm   = wid & 1;            // 0..1
    const int wn   = wid >> 1;           // 0..3
    const int m0   = blockIdx.x * 64;
    const int gid  = lane >> 2;
    const int tig  = lane & 3;

    // per-lane ldmatrix offset: lanes 0-15 -> 16 rows, lanes 16-31 -> +16B (k+8)
    const uint32_t laneoff = (uint32_t)((lane & 15) * ROWB + (lane >> 4) * 16);
    const uint32_t aBaseH = sbase + SA_H + (uint32_t)(wm * 32) * ROWB + laneoff;
    const uint32_t aBaseL = sbase + SA_L + (uint32_t)(wm * 32) * ROWB + laneoff;
    const uint32_t bBaseH = sbase + SB_H + (uint32_t)(wn * 64) * ROWB + laneoff;
    const uint32_t bBaseL = sbase + SB_L + (uint32_t)(wn * 64) * ROWB + laneoff;

    float acc[2][8][4];
#pragma unroll
    for (int mt = 0; mt < 2; mt++)
#pragma unroll
        for (int nt = 0; nt < 8; nt++)
#pragma unroll
            for (int q = 0; q < 4; q++) acc[mt][nt][q] = 0.f;

    for (int it = 0; it < 8; ++it) {
        const int kc = it * 64;
        if (it) __syncthreads();

        // ---- stage A: 64 rows x 64 k fp32 -> bf16 hi/lo in smem ----
#pragma unroll
        for (int i = 0; i < 4; i++) {
            int idx = tid + i * 256;          // 0..1023
            int r   = idx >> 4;               // 0..63
            int k4  = idx & 15;               // float4 index
            float4 v = *reinterpret_cast<const float4*>(edg + (size_t)(m0 + r) * HD + kc + 4 * k4);
            __nv_bfloat16 hx = __float2bfloat16(v.x), hy = __float2bfloat16(v.y),
                          hz = __float2bfloat16(v.z), hw = __float2bfloat16(v.w);
            __nv_bfloat16 lx = __float2bfloat16(v.x - __bfloat162float(hx)),
                          ly = __float2bfloat16(v.y - __bfloat162float(hy)),
                          lz = __float2bfloat16(v.z - __bfloat162float(hz)),
                          lw = __float2bfloat16(v.w - __bfloat162float(hw));
            int w0 = (SA_H >> 2) + r * (ROWB >> 2) + 2 * k4;
            sw[w0]     = pack_bf2(hx, hy);
            sw[w0 + 1] = pack_bf2(hz, hw);
            int w1 = (SA_L >> 2) + r * (ROWB >> 2) + 2 * k4;
            sw[w1]     = pack_bf2(lx, ly);
            sw[w1 + 1] = pack_bf2(lz, lw);
        }
        // ---- stage B: 256 n-rows x 64 k bf16 hi/lo ----
#pragma unroll
        for (int i = 0; i < 8; i++) {
            int idx = tid + i * 256;          // 0..2047
            int n   = idx >> 3;               // 0..255
            int c   = idx & 7;                // 16B chunk
            uint4 h = *reinterpret_cast<const uint4*>(g_Bhi + (size_t)n * HD + kc + c * 8);
            uint4 l = *reinterpret_cast<const uint4*>(g_Blo + (size_t)n * HD + kc + c * 8);
            *reinterpret_cast<uint4*>(smem + SB_H + n * ROWB + c * 16) = h;
            *reinterpret_cast<uint4*>(smem + SB_L + n * ROWB + c * 16) = l;
        }
        __syncthreads();

        // ---- compute: 4 k16-steps ----
#pragma unroll
        for (int ks = 0; ks < 4; ks++) {
            const uint32_t koff = ks * 32;    // 16 bf16 = 32 B
            uint32_t ah[2][4], al[2][4];
#pragma unroll
            for (int mt = 0; mt < 2; mt++) {
                ldsm4(aBaseH + (uint32_t)mt * 16 * ROWB + koff, ah[mt]);
                ldsm4(aBaseL + (uint32_t)mt * 16 * ROWB + koff, al[mt]);
            }
#pragma unroll
            for (int ng = 0; ng < 4; ng++) {
                uint32_t bh[4], bl[4];
                ldsm4(bBaseH + (uint32_t)ng * 16 * ROWB + koff, bh);
                ldsm4(bBaseL + (uint32_t)ng * 16 * ROWB + koff, bl);
#pragma unroll
                for (int mt = 0; mt < 2; mt++) {
                    // n-tile 2*ng  uses regs {0,2}; n-tile 2*ng+1 uses {1,3}
                    mma16816(acc[mt][2 * ng],     ah[mt], bh[0], bh[2]);
                    mma16816(acc[mt][2 * ng],     ah[mt], bl[0], bl[2]);
                    mma16816(acc[mt][2 * ng],     al[mt], bh[0], bh[2]);
                    mma16816(acc[mt][2 * ng + 1], ah[mt], bh[1], bh[3]);
                    mma16816(acc[mt][2 * ng + 1], ah[mt], bl[1], bl[3]);
                    mma16816(acc[mt][2 * ng + 1], al[mt], bh[1], bh[3]);
                }
            }
        }
    }

    // ---- epilogue: write fp32 M tiles ----
#pragma unroll
    for (int mt = 0; mt < 2; mt++) {
        const int row0 = m0 + wm * 32 + mt * 16 + gid;
#pragma unroll
        for (int nt = 0; nt < 8; nt++) {
            const int col = wn * 64 + nt * 8 + tig * 2;
            float2 v0 = make_float2(acc[mt][nt][0], acc[mt][nt][1]);
            float2 v1 = make_float2(acc[mt][nt][2], acc[mt][nt][3]);
            *reinterpret_cast<float2*>(g_M + (size_t)row0 * GD + col)       = v0;
            *reinterpret_cast<float2*>(g_M + (size_t)(row0 + 8) * GD + col) = v1;
        }
    }
}

// ======================= Kernel B: sim + masked softmax over b (proven) ========================
#define JB2 8

__global__ __launch_bounds__(256)
void cal_sim_stream_kernel(const float* __restrict__ chg,          // [B, N, GD]
                           const unsigned int* __restrict__ maskw, // [B, N] dtype probed
                           float* __restrict__ out)                // [N, B]
{
    __shared__ float s_M[JB2 * GD];
    __shared__ float s_sim[BB * 9];

    const int t    = threadIdx.x;
    const int lane = t & 31;
    const int warp = t >> 5;
    const int j0   = blockIdx.x * JB2;

#pragma unroll
    for (int i = 0; i < 2; i++) {
        int idx = t + i * 256;
        *reinterpret_cast<float4*>(s_M + 4 * idx) =
            *reinterpret_cast<const float4*>(g_M + (size_t)j0 * GD + 4 * idx);
    }
    __syncthreads();

    float4 m0 = reinterpret_cast<const float4*>(s_M + warp * GD)[2 * lane];
    float4 m1 = reinterpret_cast<const float4*>(s_M + warp * GD)[2 * lane + 1];

    const float* crow = chg + (size_t)(j0 + warp) * GD;

#pragma unroll 8
    for (int b = 0; b < BB; b++) {
        const float4* c = reinterpret_cast<const float4*>(crow + (size_t)b * NTOK * GD);
        float4 c0 = c[2 * lane];
        float4 c1 = c[2 * lane + 1];
        float part = c0.x * m0.x + c0.y * m0.y + c0.z * m0.z + c0.w * m0.w
                   + c1.x * m1.x + c1.y * m1.y + c1.z * m1.z + c1.w * m1.w;
#pragma unroll
        for (int s = 16; s; s >>= 1) part += __shfl_xor_sync(0xffffffffu, part, s);
        if (lane == 0) s_sim[b * 9 + warp] = part;
    }
    __syncthreads();

    bool notint = false, notfloat = false;
    for (int i = lane; i < 256; i += 32) {
        unsigned int w = maskw[i];
        notint   |= (w > 1u);
        notfloat |= (w != 0u && w != 0x3f800000u);
    }
    notint   = __any_sync(0xffffffffu, notint);
    notfloat = __any_sync(0xffffffffu, notfloat);
    const int mode = notint ? (notfloat ? 1 : 2) : 0;   // 0=int32, 1=byte, 2=float32

    {
        const int jg = j0 + warp;
        float v = s_sim[lane * 9 + warp];
        bool mk;
        if (mode == 0)      mk = reinterpret_cast<const int*>(maskw)[(size_t)lane * NTOK + jg] != 0;
        else if (mode == 1) mk = reinterpret_cast<const unsigned char*>(maskw)[(size_t)lane * NTOK + jg] != 0;
        else                mk = reinterpret_cast<const float*>(maskw)[(size_t)lane * NTOK + jg] != 0.0f;
        v = mk ? v : -1e9f;
        float mx = v;
#pragma unroll
        for (int s = 16; s; s >>= 1) mx = fmaxf(mx, __shfl_xor_sync(0xffffffffu, mx, s));
        float ev = expf(v - mx);
        float sum = ev;
#pragma unroll
        for (int s = 16; s; s >>= 1) sum += __shfl_xor_sync(0xffffffffu, sum, s);
        out[(size_t)jg * BB + lane] = ev / sum;
    }
}

extern "C" void kernel_launch(void* const* d_in, const int* in_sizes, int n_in,
                              void* d_out, int out_size)
{
    const float*        chg  = (const float*)d_in[0];        // change_embeddings [B,N,256]
    const float*        edg  = (const float*)d_in[1];        // edges_embeddings  [N,512]
    const unsigned int* mask = (const unsigned int*)d_in[2]; // mask [B,N]
    const float*        Wq   = (const float*)d_in[3];        // [128,256]
    const float*        Wk   = (const float*)d_in[4];        // [128,512]
    float*              out  = (float*)d_out;                // [N,B]

    cudaFuncSetAttribute(gemm_mma_kernel,
                         cudaFuncAttributeMaxDynamicSharedMemorySize, GEMM_SMEM);

    prep_w2_kernel<<<dim3(GD / 32, HD / 64), 256>>>(Wq, Wk);
    gemm_mma_kernel<<<NTOK / 64, 256, GEMM_SMEM>>>(edg);
    cal_sim_stream_kernel<<<NTOK / JB2, 256>>>(chg, mask, out);
}

// round 6
// speedup vs baseline: 1.7837x; 1.0503x over previous
#include <cuda_runtime.h>
#include <cuda_bf16.h>
#include <cstddef>
#include <cstdint>

// Problem constants
#define NTOK 8192   // N
#define BB   32     // batch
#define GD   256    // GRU_DIM
#define HD   512    // HAN_DIM
#define ID   128    // INNER_DIM

// ---------------- device scratch (no allocation) ----------------
__device__ float         g_M[NTOK * GD];     // 8 MB: M[j,d]
__device__ __nv_bfloat16 g_Bhi[GD * HD];     // 256 KB: W2 hi [256][512] (k-contig)
__device__ __nv_bfloat16 g_Blo[GD * HD];     // 256 KB

__device__ __forceinline__ uint32_t smem_u32(const void* p) {
    uint32_t a;
    asm("{ .reg .u64 t; cvta.to.shared.u64 t, %1; cvt.u32.u64 %0, t; }" : "=r"(a) : "l"(p));
    return a;
}
__device__ __forceinline__ void ldsm4(uint32_t addr, uint32_t* r) {
    asm volatile("ldmatrix.sync.aligned.m8n8.x4.shared.b16 {%0,%1,%2,%3}, [%4];"
                 : "=r"(r[0]), "=r"(r[1]), "=r"(r[2]), "=r"(r[3]) : "r"(addr));
}
__device__ __forceinline__ void mma16816(float* c, const uint32_t* a, uint32_t b0, uint32_t b1) {
    asm volatile(
        "mma.sync.aligned.m16n8k16.row.col.f32.bf16.bf16.f32 "
        "{%0,%1,%2,%3}, {%4,%5,%6,%7}, {%8,%9}, {%0,%1,%2,%3};"
        : "+f"(c[0]), "+f"(c[1]), "+f"(c[2]), "+f"(c[3])
        : "r"(a[0]), "r"(a[1]), "r"(a[2]), "r"(a[3]), "r"(b0), "r"(b1));
}
__device__ __forceinline__ uint32_t pack_bf2(__nv_bfloat16 lo16, __nv_bfloat16 hi16) {
    __nv_bfloat162 t; t.x = lo16; t.y = hi16;
    return *reinterpret_cast<uint32_t*>(&t);
}
__device__ __forceinline__ void cp16(uint32_t dst, const void* src) {
    asm volatile("cp.async.cg.shared.global [%0], [%1], 16;" :: "r"(dst), "l"(src) : "memory");
}

// ======================= P1: W2 = scale * Wq^T @ Wk, split to bf16 hi/lo =======================
// One output per thread. grid 512 x 256 threads: full-chip latency parallelism.
__global__ __launch_bounds__(256)
void prep_w2_kernel(const float* __restrict__ Wq, const float* __restrict__ Wk)
{
    const int d = blockIdx.x >> 1;                       // 0..255
    const int h = (blockIdx.x & 1) * 256 + threadIdx.x;  // 0..511
    float a0 = 0.f, a1 = 0.f, a2 = 0.f, a3 = 0.f;
#pragma unroll
    for (int e = 0; e < ID; e += 4) {
        a0 += Wq[(size_t)(e + 0) * GD + d] * Wk[(size_t)(e + 0) * HD + h];
        a1 += Wq[(size_t)(e + 1) * GD + d] * Wk[(size_t)(e + 1) * HD + h];
        a2 += Wq[(size_t)(e + 2) * GD + d] * Wk[(size_t)(e + 2) * HD + h];
        a3 += Wq[(size_t)(e + 3) * GD + d] * Wk[(size_t)(e + 3) * HD + h];
    }
    const float SCALE = 0.08838834764831845f;  // 128^-0.5
    float v = ((a0 + a1) + (a2 + a3)) * SCALE;
    __nv_bfloat16 hi = __float2bfloat16(v);
    __nv_bfloat16 lo = __float2bfloat16(v - __bfloat162float(hi));
    g_Bhi[(size_t)d * HD + h] = hi;
    g_Blo[(size_t)d * HD + h] = lo;
}

// ======================= A: M[8192,256] = edges @ W2^T via mma.sync bf16 split =================
// 128 CTAs, block tile 64(M)x256(N), 8 warps (2m x 4n), warp tile 32x64, K-chunks of 64.
// Double-buffered stages (1 CTA/SM, 184 KB smem). smem rows padded to 144 B.
#define ROWB   144
#define SA_H   0
#define SA_L   (SA_H + 64 * ROWB)        // 9216
#define SB_H   (SA_L + 64 * ROWB)        // 18432
#define SB_L   (SB_H + 256 * ROWB)       // 55296
#define STAGE  (SB_L + 256 * ROWB)       // 92160
#define GEMM_SMEM (2 * STAGE)            // 184320 B

__global__ __launch_bounds__(256)
void gemm_mma_kernel(const float* __restrict__ edg)   // [N, HD] fp32
{
    extern __shared__ char smem[];
    const uint32_t sbase = smem_u32(smem);

    const int tid  = threadIdx.x;
    const int lane = tid & 31;
    const int wid  = tid >> 5;
    const int wm   = wid & 1;
    const int wn   = wid >> 1;
    const int m0   = blockIdx.x * 64;
    const int gid  = lane >> 2;
    const int tig  = lane & 3;

    const uint32_t laneoff = (uint32_t)((lane & 15) * ROWB + (lane >> 4) * 16);
    const uint32_t aOffH = SA_H + (uint32_t)(wm * 32) * ROWB + laneoff;
    const uint32_t aOffL = SA_L + (uint32_t)(wm * 32) * ROWB + laneoff;
    const uint32_t bOffH = SB_H + (uint32_t)(wn * 64) * ROWB + laneoff;
    const uint32_t bOffL = SB_L + (uint32_t)(wn * 64) * ROWB + laneoff;

    // per-thread staging indices
    const int Ar  = tid >> 2;            // row 0..63  (4 float4 per row handled by 4 threads)
    const int Ak4 = tid & 3;             // base float4 within row; +4 per rep
    const int Bn  = tid >> 3;            // but B covers 256 rows via 8 reps of 32... see loop
    (void)Bn;

    float acc[2][8][4];
#pragma unroll
    for (int mt = 0; mt < 2; mt++)
#pragma unroll
        for (int nt = 0; nt < 8; nt++)
#pragma unroll
            for (int q = 0; q < 4; q++) acc[mt][nt][q] = 0.f;

    float4 ra[4];

    // ---- helpers as lambdas ----
    auto ldgA = [&](int kc) {
#pragma unroll
        for (int i = 0; i < 4; i++) {
            int idx = tid + i * 256; int r = idx >> 4, k4 = idx & 15;
            ra[i] = *reinterpret_cast<const float4*>(edg + (size_t)(m0 + r) * HD + kc + 4 * k4);
        }
    };
    auto stsA = [&](uint32_t bufbase) {
        uint32_t* sw = reinterpret_cast<uint32_t*>(smem + bufbase);
#pragma unroll
        for (int i = 0; i < 4; i++) {
            int idx = tid + i * 256; int r = idx >> 4, k4 = idx & 15;
            float4 v = ra[i];
            __nv_bfloat16 hx = __float2bfloat16(v.x), hy = __float2bfloat16(v.y),
                          hz = __float2bfloat16(v.z), hw = __float2bfloat16(v.w);
            __nv_bfloat16 lx = __float2bfloat16(v.x - __bfloat162float(hx)),
                          ly = __float2bfloat16(v.y - __bfloat162float(hy)),
                          lz = __float2bfloat16(v.z - __bfloat162float(hz)),
                          lw = __float2bfloat16(v.w - __bfloat162float(hw));
            int w0 = (SA_H >> 2) + r * (ROWB >> 2) + 2 * k4;
            sw[w0]     = pack_bf2(hx, hy);
            sw[w0 + 1] = pack_bf2(hz, hw);
            int w1 = (SA_L >> 2) + r * (ROWB >> 2) + 2 * k4;
            sw[w1]     = pack_bf2(lx, ly);
            sw[w1 + 1] = pack_bf2(lz, lw);
        }
    };
    auto cpB = [&](uint32_t bufbase, int kc) {
#pragma unroll
        for (int i = 0; i < 8; i++) {
            int idx = tid + i * 256; int n = idx >> 3, c = idx & 7;
            cp16(sbase + bufbase + SB_H + (uint32_t)(n * ROWB + c * 16),
                 g_Bhi + (size_t)n * HD + kc + c * 8);
            cp16(sbase + bufbase + SB_L + (uint32_t)(n * ROWB + c * 16),
                 g_Blo + (size_t)n * HD + kc + c * 8);
        }
        asm volatile("cp.async.commit_group;" ::: "memory");
    };

    // ---- prologue: stage 0 into buf 0 ----
    ldgA(0);
    stsA(0);
    cpB(0, 0);

    for (int it = 0; it < 8; ++it) {
        const uint32_t buf  = (uint32_t)(it & 1) * STAGE;
        const uint32_t nbuf = (uint32_t)((it & 1) ^ 1) * STAGE;

        __syncthreads();   // everyone done computing on nbuf (prev iter) & STS of buf visible
        if (it < 7) {
            ldgA((it + 1) * 64);
            cpB(nbuf, (it + 1) * 64);
            asm volatile("cp.async.wait_group 1;" ::: "memory");
        } else {
            asm volatile("cp.async.wait_group 0;" ::: "memory");
        }
        __syncthreads();   // B(it) visible to all

        // ---- compute on buf: 4 k16-steps ----
        const uint32_t aBH = sbase + buf + aOffH;
        const uint32_t aBL = sbase + buf + aOffL;
        const uint32_t bBH = sbase + buf + bOffH;
        const uint32_t bBL = sbase + buf + bOffL;
#pragma unroll
        for (int ks = 0; ks < 4; ks++) {
            const uint32_t koff = ks * 32;
            uint32_t ah[2][4], al[2][4];
#pragma unroll
            for (int mt = 0; mt < 2; mt++) {
                ldsm4(aBH + (uint32_t)mt * 16 * ROWB + koff, ah[mt]);
                ldsm4(aBL + (uint32_t)mt * 16 * ROWB + koff, al[mt]);
            }
#pragma unroll
            for (int ng = 0; ng < 4; ng++) {
                uint32_t bh[4], bl[4];
                ldsm4(bBH + (uint32_t)ng * 16 * ROWB + koff, bh);
                ldsm4(bBL + (uint32_t)ng * 16 * ROWB + koff, bl);
#pragma unroll
                for (int mt = 0; mt < 2; mt++) {
                    mma16816(acc[mt][2 * ng],     ah[mt], bh[0], bh[2]);
                    mma16816(acc[mt][2 * ng],     ah[mt], bl[0], bl[2]);
                    mma16816(acc[mt][2 * ng],     al[mt], bh[0], bh[2]);
                    mma16816(acc[mt][2 * ng + 1], ah[mt], bh[1], bh[3]);
                    mma16816(acc[mt][2 * ng + 1], ah[mt], bl[1], bl[3]);
                    mma16816(acc[mt][2 * ng + 1], al[mt], bh[1], bh[3]);
                }
            }
        }

        if (it < 7) stsA(nbuf);   // convert+store A(it+1) after compute (LDG latency hidden)
    }

    // ---- epilogue: write fp32 M tiles ----
#pragma unroll
    for (int mt = 0; mt < 2; mt++) {
        const int row0 = m0 + wm * 32 + mt * 16 + gid;
#pragma unroll
        for (int nt = 0; nt < 8; nt++) {
            const int col = wn * 64 + nt * 8 + tig * 2;
            float2 v0 = make_float2(acc[mt][nt][0], acc[mt][nt][1]);
            float2 v1 = make_float2(acc[mt][nt][2], acc[mt][nt][3]);
            *reinterpret_cast<float2*>(g_M + (size_t)row0 * GD + col)       = v0;
            *reinterpret_cast<float2*>(g_M + (size_t)(row0 + 8) * GD + col) = v1;
        }
    }
}

// ======================= Kernel B: sim + masked softmax over b =======================
#define JB2 8

__global__ __launch_bounds__(256)
void cal_sim_stream_kernel(const float* __restrict__ chg,          // [B, N, GD]
                           const unsigned int* __restrict__ maskw, // [B, N] dtype probed
                           float* __restrict__ out)                // [N, B]
{
    __shared__ float s_M[JB2 * GD];
    __shared__ float s_sim[BB * 9];

    const int t    = threadIdx.x;
    const int lane = t & 31;
    const int warp = t >> 5;
    const int j0   = blockIdx.x * JB2;

#pragma unroll
    for (int i = 0; i < 2; i++) {
        int idx = t + i * 256;
        *reinterpret_cast<float4*>(s_M + 4 * idx) =
            *reinterpret_cast<const float4*>(g_M + (size_t)j0 * GD + 4 * idx);
    }
    __syncthreads();

    float4 m0 = reinterpret_cast<const float4*>(s_M + warp * GD)[2 * lane];
    float4 m1 = reinterpret_cast<const float4*>(s_M + warp * GD)[2 * lane + 1];

    const float* crow = chg + (size_t)(j0 + warp) * GD;

#pragma unroll 8
    for (int b = 0; b < BB; b++) {
        const float4* c = reinterpret_cast<const float4*>(crow + (size_t)b * NTOK * GD);
        float4 c0 = __ldcs(c + 2 * lane);        // streaming: single-use data, evict-first
        float4 c1 = __ldcs(c + 2 * lane + 1);
        float part = c0.x * m0.x + c0.y * m0.y + c0.z * m0.z + c0.w * m0.w
                   + c1.x * m1.x + c1.y * m1.y + c1.z * m1.z + c1.w * m1.w;
#pragma unroll
        for (int s = 16; s; s >>= 1) part += __shfl_xor_sync(0xffffffffu, part, s);
        if (lane == 0) s_sim[b * 9 + warp] = part;
    }
    __syncthreads();

    bool notint = false, notfloat = false;
    for (int i = lane; i < 256; i += 32) {
        unsigned int w = maskw[i];
        notint   |= (w > 1u);
        notfloat |= (w != 0u && w != 0x3f800000u);
    }
    notint   = __any_sync(0xffffffffu, notint);
    notfloat = __any_sync(0xffffffffu, notfloat);
    const int mode = notint ? (notfloat ? 1 : 2) : 0;   // 0=int32, 1=byte, 2=float32

    {
        const int jg = j0 + warp;
        float v = s_sim[lane * 9 + warp];
        bool mk;
        if (mode == 0)      mk = reinterpret_cast<const int*>(maskw)[(size_t)lane * NTOK + jg] != 0;
        else if (mode == 1) mk = reinterpret_cast<const unsigned char*>(maskw)[(size_t)lane * NTOK + jg] != 0;
        else                mk = reinterpret_cast<const float*>(maskw)[(size_t)lane * NTOK + jg] != 0.0f;
        v = mk ? v : -1e9f;
        float mx = v;
#pragma unroll
        for (int s = 16; s; s >>= 1) mx = fmaxf(mx, __shfl_xor_sync(0xffffffffu, mx, s));
        float ev = expf(v - mx);
        float sum = ev;
#pragma unroll
        for (int s = 16; s; s >>= 1) sum += __shfl_xor_sync(0xffffffffu, sum, s);
        out[(size_t)jg * BB + lane] = ev / sum;
    }
}

extern "C" void kernel_launch(void* const* d_in, const int* in_sizes, int n_in,
                              void* d_out, int out_size)
{
    const float*        chg  = (const float*)d_in[0];        // change_embeddings [B,N,256]
    const float*        edg  = (const float*)d_in[1];        // edges_embeddings  [N,512]
    const unsigned int* mask = (const unsigned int*)d_in[2]; // mask [B,N]
    const float*        Wq   = (const float*)d_in[3];        // [128,256]
    const float*        Wk   = (const float*)d_in[4];        // [128,512]
    float*              out  = (float*)d_out;                // [N,B]

    cudaFuncSetAttribute(gemm_mma_kernel,
                         cudaFuncAttributeMaxDynamicSharedMemorySize, GEMM_SMEM);

    prep_w2_kernel<<<512, 256>>>(Wq, Wk);
    gemm_mma_kernel<<<NTOK / 64, 256, GEMM_SMEM>>>(edg);
    cal_sim_stream_kernel<<<NTOK / JB2, 256>>>(chg, mask, out);
}

// round 8
// speedup vs baseline: 1.9200x; 1.0764x over previous
#include <cuda_runtime.h>
#include <cuda_bf16.h>
#include <cstddef>
#include <cstdint>

// Problem constants
#define NTOK 8192   // N
#define BB   32     // batch
#define GD   256    // GRU_DIM
#define HD   512    // HAN_DIM
#define ID   128    // INNER_DIM

// ---------------- device scratch (no allocation) ----------------
__device__ float         g_M[NTOK * GD];      // 8 MB: M[j,d]
__device__ __nv_bfloat16 g_Khi[NTOK * ID];    // 2 MB: K[j,e] hi
__device__ __nv_bfloat16 g_Klo[NTOK * ID];    // 2 MB
__device__ __nv_bfloat16 g_WkHi[ID * HD];     // 128 KB: Wk[e,h] hi (k-contig rows)
__device__ __nv_bfloat16 g_WkLo[ID * HD];     // 128 KB
__device__ __nv_bfloat16 g_WqTHi[GD * ID];    // 64 KB: SCALE * WqT[d,e] hi (k-contig rows)
__device__ __nv_bfloat16 g_WqTLo[GD * ID];    // 64 KB

__device__ __forceinline__ uint32_t smem_u32(const void* p) {
    uint32_t a;
    asm("{ .reg .u64 t; cvta.to.shared.u64 t, %1; cvt.u32.u64 %0, t; }" : "=r"(a) : "l"(p));
    return a;
}
__device__ __forceinline__ void ldsm4(uint32_t addr, uint32_t* r) {
    asm volatile("ldmatrix.sync.aligned.m8n8.x4.shared.b16 {%0,%1,%2,%3}, [%4];"
                 : "=r"(r[0]), "=r"(r[1]), "=r"(r[2]), "=r"(r[3]) : "r"(addr));
}
__device__ __forceinline__ void mma16816(float* c, const uint32_t* a, uint32_t b0, uint32_t b1) {
    asm volatile(
        "mma.sync.aligned.m16n8k16.row.col.f32.bf16.bf16.f32 "
        "{%0,%1,%2,%3}, {%4,%5,%6,%7}, {%8,%9}, {%0,%1,%2,%3};"
        : "+f"(c[0]), "+f"(c[1]), "+f"(c[2]), "+f"(c[3])
        : "r"(a[0]), "r"(a[1]), "r"(a[2]), "r"(a[3]), "r"(b0), "r"(b1));
}
__device__ __forceinline__ uint32_t pack_bf2(__nv_bfloat16 lo16, __nv_bfloat16 hi16) {
    __nv_bfloat162 t; t.x = lo16; t.y = hi16;
    return *reinterpret_cast<uint32_t*>(&t);
}
__device__ __forceinline__ void cp16(uint32_t dst, const void* src) {
    asm volatile("cp.async.cg.shared.global [%0], [%1], 16;" :: "r"(dst), "l"(src) : "memory");
}
__device__ __forceinline__ void split_bf(float v, __nv_bfloat16& hi, __nv_bfloat16& lo) {
    hi = __float2bfloat16(v);
    lo = __float2bfloat16(v - __bfloat162float(hi));
}

// ======================= P: split Wk (copy) + transpose/split (SCALE * Wq) ====================
// blocks 0..15: Wk fp32 -> bf16 hi/lo (same layout). blocks 16..47: Wq [e,d] -> SCALE*WqT [d,e].
__global__ __launch_bounds__(256)
void prep_split_kernel(const float* __restrict__ Wq, const float* __restrict__ Wk)
{
    const int tid = threadIdx.x;
    if (blockIdx.x < 16) {
        // Wk: 65536 floats = 16384 float4; 16 blocks x 256 thr x 4
#pragma unroll
        for (int i = 0; i < 4; i++) {
            int idx = (blockIdx.x * 1024) + tid + i * 256;   // float4 index
            float4 v = *reinterpret_cast<const float4*>(Wk + 4 * (size_t)idx);
            __nv_bfloat16 hx, lx, hy, ly, hz, lz, hw, lw;
            split_bf(v.x, hx, lx); split_bf(v.y, hy, ly);
            split_bf(v.z, hz, lz); split_bf(v.w, hw, lw);
            *reinterpret_cast<uint32_t*>(g_WkHi + 4 * (size_t)idx)     = pack_bf2(hx, hy);
            *reinterpret_cast<uint32_t*>(g_WkHi + 4 * (size_t)idx + 2) = pack_bf2(hz, hw);
            *reinterpret_cast<uint32_t*>(g_WkLo + 4 * (size_t)idx)     = pack_bf2(lx, ly);
            *reinterpret_cast<uint32_t*>(g_WkLo + 4 * (size_t)idx + 2) = pack_bf2(lz, lw);
        }
    } else {
        __shared__ float s[32][33];
        const int b  = blockIdx.x - 16;   // 0..31
        const int e0 = (b & 3) * 32;
        const int d0 = (b >> 2) * 32;
        const int r  = tid >> 5;          // 0..7
        const int c  = tid & 31;
        const float SCALE = 0.08838834764831845f;  // 128^-0.5
#pragma unroll
        for (int i = 0; i < 4; i++)
            s[r + i * 8][c] = Wq[(size_t)(e0 + r + i * 8) * GD + d0 + c];   // s[e][d]
        __syncthreads();
#pragma unroll
        for (int i = 0; i < 4; i++) {
            int dl = r + i * 8;           // local d
            float v = s[c][dl] * SCALE;   // SCALE * WqT[d][e]  (scale BEFORE split)
            __nv_bfloat16 hi, lo; split_bf(v, hi, lo);
            g_WqTHi[(size_t)(d0 + dl) * ID + e0 + c] = hi;
            g_WqTLo[(size_t)(d0 + dl) * ID + e0 + c] = lo;
        }
    }
}

// ======================= G1: K[8192,128] = E[8192,512] @ Wk^T (bf16 3-term) ====================
// 128 CTAs, block tile 64(M)x128(N), 8 warps (2m x 4n), warp 32x32, K-chunks 64, double buffer.
#define ROWB   144
#define G1_SA_H 0
#define G1_SA_L (G1_SA_H + 64 * ROWB)      // 9216
#define G1_SB_H (G1_SA_L + 64 * ROWB)      // 18432
#define G1_SB_L (G1_SB_H + 128 * ROWB)     // 36864
#define G1_STAGE (G1_SB_L + 128 * ROWB)    // 55296
#define G1_SMEM (2 * G1_STAGE)             // 110592

__global__ __launch_bounds__(256)
void gemm1_kernel(const float* __restrict__ edg)   // [N, HD] fp32
{
    extern __shared__ char smem[];
    const uint32_t sbase = smem_u32(smem);

    const int tid  = threadIdx.x;
    const int lane = tid & 31;
    const int wid  = tid >> 5;
    const int wm   = wid & 1;
    const int wn   = wid >> 1;            // 0..3 -> n offset wn*32
    const int m0   = blockIdx.x * 64;
    const int gid  = lane >> 2;
    const int tig  = lane & 3;

    const uint32_t laneoff = (uint32_t)((lane & 15) * ROWB + (lane >> 4) * 16);
    const uint32_t aOffH = G1_SA_H + (uint32_t)(wm * 32) * ROWB + laneoff;
    const uint32_t aOffL = G1_SA_L + (uint32_t)(wm * 32) * ROWB + laneoff;
    const uint32_t bOffH = G1_SB_H + (uint32_t)(wn * 32) * ROWB + laneoff;
    const uint32_t bOffL = G1_SB_L + (uint32_t)(wn * 32) * ROWB + laneoff;

    float acc[2][4][4];
#pragma unroll
    for (int mt = 0; mt < 2; mt++)
#pragma unroll
        for (int nt = 0; nt < 4; nt++)
#pragma unroll
            for (int q = 0; q < 4; q++) acc[mt][nt][q] = 0.f;

    float4 ra[4];
    auto ldgA = [&](int kc) {
#pragma unroll
        for (int i = 0; i < 4; i++) {
            int idx = tid + i * 256; int r = idx >> 4, k4 = idx & 15;
            ra[i] = *reinterpret_cast<const float4*>(edg + (size_t)(m0 + r) * HD + kc + 4 * k4);
        }
    };
    auto stsA = [&](uint32_t bufbase) {
        uint32_t* sw = reinterpret_cast<uint32_t*>(smem + bufbase);
#pragma unroll
        for (int i = 0; i < 4; i++) {
            int idx = tid + i * 256; int r = idx >> 4, k4 = idx & 15;
            float4 v = ra[i];
            __nv_bfloat16 hx, lx, hy, ly, hz, lz, hw, lw;
            split_bf(v.x, hx, lx); split_bf(v.y, hy, ly);
            split_bf(v.z, hz, lz); split_bf(v.w, hw, lw);
            int w0 = (G1_SA_H >> 2) + r * (ROWB >> 2) + 2 * k4;
            sw[w0]     = pack_bf2(hx, hy);
            sw[w0 + 1] = pack_bf2(hz, hw);
            int w1 = (G1_SA_L >> 2) + r * (ROWB >> 2) + 2 * k4;
            sw[w1]     = pack_bf2(lx, ly);
            sw[w1 + 1] = pack_bf2(lz, lw);
        }
    };
    auto cpB = [&](uint32_t bufbase, int kc) {
        // 128 n-rows x 64 k bf16: 1024 16B chunks per array
#pragma unroll
        for (int i = 0; i < 4; i++) {
            int idx = tid + i * 256; int n = idx >> 3, c = idx & 7;
            cp16(sbase + bufbase + G1_SB_H + (uint32_t)(n * ROWB + c * 16),
                 g_WkHi + (size_t)n * HD + kc + c * 8);
            cp16(sbase + bufbase + G1_SB_L + (uint32_t)(n * ROWB + c * 16),
                 g_WkLo + (size_t)n * HD + kc + c * 8);
        }
        asm volatile("cp.async.commit_group;" ::: "memory");
    };

    ldgA(0);
    stsA(0);
    cpB(0, 0);

    for (int it = 0; it < 8; ++it) {
        const uint32_t buf  = (uint32_t)(it & 1) * G1_STAGE;
        const uint32_t nbuf = (uint32_t)((it & 1) ^ 1) * G1_STAGE;

        __syncthreads();
        if (it < 7) {
            ldgA((it + 1) * 64);
            cpB(nbuf, (it + 1) * 64);
            asm volatile("cp.async.wait_group 1;" ::: "memory");
        } else {
            asm volatile("cp.async.wait_group 0;" ::: "memory");
        }
        __syncthreads();

        const uint32_t aBH = sbase + buf + aOffH;
        const uint32_t aBL = sbase + buf + aOffL;
        const uint32_t bBH = sbase + buf + bOffH;
        const uint32_t bBL = sbase + buf + bOffL;
#pragma unroll
        for (int ks = 0; ks < 4; ks++) {
            const uint32_t koff = ks * 32;
            uint32_t ah[2][4], al[2][4];
#pragma unroll
            for (int mt = 0; mt < 2; mt++) {
                ldsm4(aBH + (uint32_t)mt * 16 * ROWB + koff, ah[mt]);
                ldsm4(aBL + (uint32_t)mt * 16 * ROWB + koff, al[mt]);
            }
#pragma unroll
            for (int ng = 0; ng < 2; ng++) {
                uint32_t bh[4], bl[4];
                ldsm4(bBH + (uint32_t)ng * 16 * ROWB + koff, bh);
                ldsm4(bBL + (uint32_t)ng * 16 * ROWB + koff, bl);
#pragma unroll
                for (int mt = 0; mt < 2; mt++) {
                    mma16816(acc[mt][2 * ng],     ah[mt], bh[0], bh[2]);
                    mma16816(acc[mt][2 * ng],     ah[mt], bl[0], bl[2]);
                    mma16816(acc[mt][2 * ng],     al[mt], bh[0], bh[2]);
                    mma16816(acc[mt][2 * ng + 1], ah[mt], bh[1], bh[3]);
                    mma16816(acc[mt][2 * ng + 1], ah[mt], bl[1], bl[3]);
                    mma16816(acc[mt][2 * ng + 1], al[mt], bh[1], bh[3]);
                }
            }
        }

        if (it < 7) stsA(nbuf);
    }

    // epilogue: split fp32 acc -> K hi/lo bf16
#pragma unroll
    for (int mt = 0; mt < 2; mt++) {
        const int row0 = m0 + wm * 32 + mt * 16 + gid;
#pragma unroll
        for (int nt = 0; nt < 4; nt++) {
            const int col = wn * 32 + nt * 8 + tig * 2;
            __nv_bfloat16 h0, l0, h1, l1, h2, l2, h3, l3;
            split_bf(acc[mt][nt][0], h0, l0); split_bf(acc[mt][nt][1], h1, l1);
            split_bf(acc[mt][nt][2], h2, l2); split_bf(acc[mt][nt][3], h3, l3);
            *reinterpret_cast<uint32_t*>(g_Khi + (size_t)row0 * ID + col)       = pack_bf2(h0, h1);
            *reinterpret_cast<uint32_t*>(g_Klo + (size_t)row0 * ID + col)       = pack_bf2(l0, l1);
            *reinterpret_cast<uint32_t*>(g_Khi + (size_t)(row0 + 8) * ID + col) = pack_bf2(h2, h3);
            *reinterpret_cast<uint32_t*>(g_Klo + (size_t)(row0 + 8) * ID + col) = pack_bf2(l2, l3);
        }
    }
}

// ======================= G2: M[8192,256] = K[8192,128] @ (SCALE*WqT)^T (bf16 3-term) ===========
// 128 CTAs, block tile 64(M)x256(N), 8 warps (2m x 4n), warp 32x64, 2 K-chunks of 64, 2 buffers.
#define G2_SA_H 0
#define G2_SA_L (G2_SA_H + 64 * ROWB)       // 9216
#define G2_SB_H (G2_SA_L + 64 * ROWB)       // 18432
#define G2_SB_L (G2_SB_H + 256 * ROWB)      // 55296
#define G2_STAGE (G2_SB_L + 256 * ROWB)     // 92160
#define G2_SMEM (2 * G2_STAGE)              // 184320

__global__ __launch_bounds__(256)
void gemm2_kernel()
{
    extern __shared__ char smem[];
    const uint32_t sbase = smem_u32(smem);

    const int tid  = threadIdx.x;
    const int lane = tid & 31;
    const int wid  = tid >> 5;
    const int wm   = wid & 1;
    const int wn   = wid >> 1;
    const int m0   = blockIdx.x * 64;
    const int gid  = lane >> 2;
    const int tig  = lane & 3;

    const uint32_t laneoff = (uint32_t)((lane & 15) * ROWB + (lane >> 4) * 16);
    const uint32_t aOffH = G2_SA_H + (uint32_t)(wm * 32) * ROWB + laneoff;
    const uint32_t aOffL = G2_SA_L + (uint32_t)(wm * 32) * ROWB + laneoff;
    const uint32_t bOffH = G2_SB_H + (uint32_t)(wn * 64) * ROWB + laneoff;
    const uint32_t bOffL = G2_SB_L + (uint32_t)(wn * 64) * ROWB + laneoff;

    float acc[2][8][4];
#pragma unroll
    for (int mt = 0; mt < 2; mt++)
#pragma unroll
        for (int nt = 0; nt < 8; nt++)
#pragma unroll
            for (int q = 0; q < 4; q++) acc[mt][nt][q] = 0.f;

    auto cpStage = [&](uint32_t bufbase, int kc) {
        // A: 64 rows x 64k bf16 = 512 chunks per array
#pragma unroll
        for (int i = 0; i < 2; i++) {
            int idx = tid + i * 256; int n = idx >> 3, c = idx & 7;
            cp16(sbase + bufbase + G2_SA_H + (uint32_t)(n * ROWB + c * 16),
                 g_Khi + (size_t)(m0 + n) * ID + kc + c * 8);
            cp16(sbase + bufbase + G2_SA_L + (uint32_t)(n * ROWB + c * 16),
                 g_Klo + (size_t)(m0 + n) * ID + kc + c * 8);
        }
        // B: 256 rows x 64k bf16 = 2048 chunks per array
#pragma unroll
        for (int i = 0; i < 8; i++) {
            int idx = tid + i * 256; int n = idx >> 3, c = idx & 7;
            cp16(sbase + bufbase + G2_SB_H + (uint32_t)(n * ROWB + c * 16),
                 g_WqTHi + (size_t)n * ID + kc + c * 8);
            cp16(sbase + bufbase + G2_SB_L + (uint32_t)(n * ROWB + c * 16),
                 g_WqTLo + (size_t)n * ID + kc + c * 8);
        }
        asm volatile("cp.async.commit_group;" ::: "memory");
    };

    auto compute = [&](uint32_t buf) {
        const uint32_t aBH = sbase + buf + aOffH;
        const uint32_t aBL = sbase + buf + aOffL;
        const uint32_t bBH = sbase + buf + bOffH;
        const uint32_t bBL = sbase + buf + bOffL;
#pragma unroll
        for (int ks = 0; ks < 4; ks++) {
            const uint32_t koff = ks * 32;
            uint32_t ah[2][4], al[2][4];
#pragma unroll
            for (int mt = 0; mt < 2; mt++) {
                ldsm4(aBH + (uint32_t)mt * 16 * ROWB + koff, ah[mt]);
                ldsm4(aBL + (uint32_t)mt * 16 * ROWB + koff, al[mt]);
            }
#pragma unroll
            for (int ng = 0; ng < 4; ng++) {
                uint32_t bh[4], bl[4];
                ldsm4(bBH + (uint32_t)ng * 16 * ROWB + koff, bh);
                ldsm4(bBL + (uint32_t)ng * 16 * ROWB + koff, bl);
#pragma unroll
                for (int mt = 0; mt < 2; mt++) {
                    mma16816(acc[mt][2 * ng],     ah[mt], bh[0], bh[2]);
                    mma16816(acc[mt][2 * ng],     ah[mt], bl[0], bl[2]);
                    mma16816(acc[mt][2 * ng],     al[mt], bh[0], bh[2]);
                    mma16816(acc[mt][2 * ng + 1], ah[mt], bh[1], bh[3]);
                    mma16816(acc[mt][2 * ng + 1], ah[mt], bl[1], bl[3]);
                    mma16816(acc[mt][2 * ng + 1], al[mt], bh[1], bh[3]);
                }
            }
        }
    };

    cpStage(0, 0);
    cpStage(G2_STAGE, 64);
    asm volatile("cp.async.wait_group 1;" ::: "memory");
    __syncthreads();
    compute(0);
    asm volatile("cp.async.wait_group 0;" ::: "memory");
    __syncthreads();
    compute(G2_STAGE);

#pragma unroll
    for (int mt = 0; mt < 2; mt++) {
        const int row0 = m0 + wm * 32 + mt * 16 + gid;
#pragma unroll
        for (int nt = 0; nt < 8; nt++) {
            const int col = wn * 64 + nt * 8 + tig * 2;
            float2 v0 = make_float2(acc[mt][nt][0], acc[mt][nt][1]);
            float2 v1 = make_float2(acc[mt][nt][2], acc[mt][nt][3]);
            *reinterpret_cast<float2*>(g_M + (size_t)row0 * GD + col)       = v0;
            *reinterpret_cast<float2*>(g_M + (size_t)(row0 + 8) * GD + col) = v1;
        }
    }
}

// ======================= Kernel B: sim + masked softmax over b (proven) ========================
#define JB2 8

__global__ __launch_bounds__(256)
void cal_sim_stream_kernel(const float* __restrict__ chg,          // [B, N, GD]
                           const unsigned int* __restrict__ maskw, // [B, N] dtype probed
                           float* __restrict__ out)                // [N, B]
{
    __shared__ float s_M[JB2 * GD];
    __shared__ float s_sim[BB * 9];

    const int t    = threadIdx.x;
    const int lane = t & 31;
    const int warp = t >> 5;
    const int j0   = blockIdx.x * JB2;

#pragma unroll
    for (int i = 0; i < 2; i++) {
        int idx = t + i * 256;
        *reinterpret_cast<float4*>(s_M + 4 * idx) =
            *reinterpret_cast<const float4*>(g_M + (size_t)j0 * GD + 4 * idx);
    }
    __syncthreads();

    float4 m0 = reinterpret_cast<const float4*>(s_M + warp * GD)[2 * lane];
    float4 m1 = reinterpret_cast<const float4*>(s_M + warp * GD)[2 * lane + 1];

    const float* crow = chg + (size_t)(j0 + warp) * GD;

#pragma unroll 8
    for (int b = 0; b < BB; b++) {
        const float4* c = reinterpret_cast<const float4*>(crow + (size_t)b * NTOK * GD);
        float4 c0 = __ldcs(c + 2 * lane);
        float4 c1 = __ldcs(c + 2 * lane + 1);
        float part = c0.x * m0.x + c0.y * m0.y + c0.z * m0.z + c0.w * m0.w
                   + c1.x * m1.x + c1.y * m1.y + c1.z * m1.z + c1.w * m1.w;
#pragma unroll
        for (int s = 16; s; s >>= 1) part += __shfl_xor_sync(0xffffffffu, part, s);
        if (lane == 0) s_sim[b * 9 + warp] = part;
    }
    __syncthreads();

    bool notint = false, notfloat = false;
    for (int i = lane; i < 256; i += 32) {
        unsigned int w = maskw[i];
        notint   |= (w > 1u);
        notfloat |= (w != 0u && w != 0x3f800000u);
    }
    notint   = __any_sync(0xffffffffu, notint);
    notfloat = __any_sync(0xffffffffu, notfloat);
    const int mode = notint ? (notfloat ? 1 : 2) : 0;   // 0=int32, 1=byte, 2=float32

    {
        const int jg = j0 + warp;
        float v = s_sim[lane * 9 + warp];
        bool mk;
        if (mode == 0)      mk = reinterpret_cast<const int*>(maskw)[(size_t)lane * NTOK + jg] != 0;
        else if (mode == 1) mk = reinterpret_cast<const unsigned char*>(maskw)[(size_t)lane * NTOK + jg] != 0;
        else                mk = reinterpret_cast<const float*>(maskw)[(size_t)lane * NTOK + jg] != 0.0f;
        v = mk ? v : -1e9f;
        float mx = v;
#pragma unroll
        for (int s = 16; s; s >>= 1) mx = fmaxf(mx, __shfl_xor_sync(0xffffffffu, mx, s));
        float ev = expf(v - mx);
        float sum = ev;
#pragma unroll
        for (int s = 16; s; s >>= 1) sum += __shfl_xor_sync(0xffffffffu, sum, s);
        out[(size_t)jg * BB + lane] = ev / sum;
    }
}

extern "C" void kernel_launch(void* const* d_in, const int* in_sizes, int n_in,
                              void* d_out, int out_size)
{
    const float*        chg  = (const float*)d_in[0];        // change_embeddings [B,N,256]
    const float*        edg  = (const float*)d_in[1];        // edges_embeddings  [N,512]
    const unsigned int* mask = (const unsigned int*)d_in[2]; // mask [B,N]
    const float*        Wq   = (const float*)d_in[3];        // [128,256]
    const float*        Wk   = (const float*)d_in[4];        // [128,512]
    float*              out  = (float*)d_out;                // [N,B]

    cudaFuncSetAttribute(gemm1_kernel,
                         cudaFuncAttributeMaxDynamicSharedMemorySize, G1_SMEM);
    cudaFuncSetAttribute(gemm2_kernel,
                         cudaFuncAttributeMaxDynamicSharedMemorySize, G2_SMEM);

    prep_split_kernel<<<48, 256>>>(Wq, Wk);
    gemm1_kernel<<<NTOK / 64, 256, G1_SMEM>>>(edg);
    gemm2_kernel<<<NTOK / 64, 256, G2_SMEM>>>();
    cal_sim_stream_kernel<<<NTOK / JB2, 256>>>(chg, mask, out);
}

// round 9
// speedup vs baseline: 2.0231x; 1.0537x over previous
#include <cuda_runtime.h>
#include <cuda_bf16.h>
#include <cstddef>
#include <cstdint>

// Problem constants
#define NTOK 8192   // N
#define BB   32     // batch
#define GD   256    // GRU_DIM
#define HD   512    // HAN_DIM
#define ID   128    // INNER_DIM

// ---------------- device scratch (no allocation) ----------------
__device__ float         g_M[NTOK * GD];      // 8 MB: M[j,d]
__device__ __nv_bfloat16 g_Khi[NTOK * ID];    // 2 MB: K[j,e] hi
__device__ __nv_bfloat16 g_Klo[NTOK * ID];    // 2 MB
__device__ __nv_bfloat16 g_WkHi[ID * HD];     // 128 KB: Wk[e,h] hi (k-contig rows)
__device__ __nv_bfloat16 g_WkLo[ID * HD];     // 128 KB
__device__ __nv_bfloat16 g_WqTHi[GD * ID];    // 64 KB: SCALE * WqT[d,e] hi (k-contig rows)
__device__ __nv_bfloat16 g_WqTLo[GD * ID];    // 64 KB

__device__ __forceinline__ uint32_t smem_u32(const void* p) {
    uint32_t a;
    asm("{ .reg .u64 t; cvta.to.shared.u64 t, %1; cvt.u32.u64 %0, t; }" : "=r"(a) : "l"(p));
    return a;
}
__device__ __forceinline__ void ldsm4(uint32_t addr, uint32_t* r) {
    asm volatile("ldmatrix.sync.aligned.m8n8.x4.shared.b16 {%0,%1,%2,%3}, [%4];"
                 : "=r"(r[0]), "=r"(r[1]), "=r"(r[2]), "=r"(r[3]) : "r"(addr));
}
__device__ __forceinline__ void mma16816(float* c, const uint32_t* a, uint32_t b0, uint32_t b1) {
    asm volatile(
        "mma.sync.aligned.m16n8k16.row.col.f32.bf16.bf16.f32 "
        "{%0,%1,%2,%3}, {%4,%5,%6,%7}, {%8,%9}, {%0,%1,%2,%3};"
        : "+f"(c[0]), "+f"(c[1]), "+f"(c[2]), "+f"(c[3])
        : "r"(a[0]), "r"(a[1]), "r"(a[2]), "r"(a[3]), "r"(b0), "r"(b1));
}
__device__ __forceinline__ uint32_t pack_bf2(__nv_bfloat16 lo16, __nv_bfloat16 hi16) {
    __nv_bfloat162 t; t.x = lo16; t.y = hi16;
    return *reinterpret_cast<uint32_t*>(&t);
}
__device__ __forceinline__ void cp16(uint32_t dst, const void* src) {
    asm volatile("cp.async.cg.shared.global [%0], [%1], 16;" :: "r"(dst), "l"(src) : "memory");
}
__device__ __forceinline__ void split_bf(float v, __nv_bfloat16& hi, __nv_bfloat16& lo) {
    hi = __float2bfloat16(v);
    lo = __float2bfloat16(v - __bfloat162float(hi));
}

// ======================= P: split Wk (copy) + transpose/split (SCALE * Wq) ====================
__global__ __launch_bounds__(256)
void prep_split_kernel(const float* __restrict__ Wq, const float* __restrict__ Wk)
{
    const int tid = threadIdx.x;
    if (blockIdx.x < 16) {
#pragma unroll
        for (int i = 0; i < 4; i++) {
            int idx = (blockIdx.x * 1024) + tid + i * 256;   // float4 index
            float4 v = *reinterpret_cast<const float4*>(Wk + 4 * (size_t)idx);
            __nv_bfloat16 hx, lx, hy, ly, hz, lz, hw, lw;
            split_bf(v.x, hx, lx); split_bf(v.y, hy, ly);
            split_bf(v.z, hz, lz); split_bf(v.w, hw, lw);
            *reinterpret_cast<uint32_t*>(g_WkHi + 4 * (size_t)idx)     = pack_bf2(hx, hy);
            *reinterpret_cast<uint32_t*>(g_WkHi + 4 * (size_t)idx + 2) = pack_bf2(hz, hw);
            *reinterpret_cast<uint32_t*>(g_WkLo + 4 * (size_t)idx)     = pack_bf2(lx, ly);
            *reinterpret_cast<uint32_t*>(g_WkLo + 4 * (size_t)idx + 2) = pack_bf2(lz, lw);
        }
    } else {
        __shared__ float s[32][33];
        const int b  = blockIdx.x - 16;   // 0..31
        const int e0 = (b & 3) * 32;
        const int d0 = (b >> 2) * 32;
        const int r  = tid >> 5;          // 0..7
        const int c  = tid & 31;
        const float SCALE = 0.08838834764831845f;  // 128^-0.5
#pragma unroll
        for (int i = 0; i < 4; i++)
            s[r + i * 8][c] = Wq[(size_t)(e0 + r + i * 8) * GD + d0 + c];   // s[e][d]
        __syncthreads();
#pragma unroll
        for (int i = 0; i < 4; i++) {
            int dl = r + i * 8;
            float v = s[c][dl] * SCALE;   // SCALE * WqT[d][e]  (scale BEFORE split)
            __nv_bfloat16 hi, lo; split_bf(v, hi, lo);
            g_WqTHi[(size_t)(d0 + dl) * ID + e0 + c] = hi;
            g_WqTLo[(size_t)(d0 + dl) * ID + e0 + c] = lo;
        }
    }
}

// ======================= G1: K[8192,128] = E[8192,512] @ Wk^T (bf16 3-term) ====================
#define ROWB   144
#define G1_SA_H 0
#define G1_SA_L (G1_SA_H + 64 * ROWB)
#define G1_SB_H (G1_SA_L + 64 * ROWB)
#define G1_SB_L (G1_SB_H + 128 * ROWB)
#define G1_STAGE (G1_SB_L + 128 * ROWB)    // 55296
#define G1_SMEM (2 * G1_STAGE)             // 110592

__global__ __launch_bounds__(256)
void gemm1_kernel(const float* __restrict__ edg)   // [N, HD] fp32
{
    extern __shared__ char smem[];
    const uint32_t sbase = smem_u32(smem);

    const int tid  = threadIdx.x;
    const int lane = tid & 31;
    const int wid  = tid >> 5;
    const int wm   = wid & 1;
    const int wn   = wid >> 1;
    const int m0   = blockIdx.x * 64;
    const int gid  = lane >> 2;
    const int tig  = lane & 3;

    const uint32_t laneoff = (uint32_t)((lane & 15) * ROWB + (lane >> 4) * 16);
    const uint32_t aOffH = G1_SA_H + (uint32_t)(wm * 32) * ROWB + laneoff;
    const uint32_t aOffL = G1_SA_L + (uint32_t)(wm * 32) * ROWB + laneoff;
    const uint32_t bOffH = G1_SB_H + (uint32_t)(wn * 32) * ROWB + laneoff;
    const uint32_t bOffL = G1_SB_L + (uint32_t)(wn * 32) * ROWB + laneoff;

    float acc[2][4][4];
#pragma unroll
    for (int mt = 0; mt < 2; mt++)
#pragma unroll
        for (int nt = 0; nt < 4; nt++)
#pragma unroll
            for (int q = 0; q < 4; q++) acc[mt][nt][q] = 0.f;

    float4 ra[4];
    auto ldgA = [&](int kc) {
#pragma unroll
        for (int i = 0; i < 4; i++) {
            int idx = tid + i * 256; int r = idx >> 4, k4 = idx & 15;
            ra[i] = *reinterpret_cast<const float4*>(edg + (size_t)(m0 + r) * HD + kc + 4 * k4);
        }
    };
    auto stsA = [&](uint32_t bufbase) {
        uint32_t* sw = reinterpret_cast<uint32_t*>(smem + bufbase);
#pragma unroll
        for (int i = 0; i < 4; i++) {
            int idx = tid + i * 256; int r = idx >> 4, k4 = idx & 15;
            float4 v = ra[i];
            __nv_bfloat16 hx, lx, hy, ly, hz, lz, hw, lw;
            split_bf(v.x, hx, lx); split_bf(v.y, hy, ly);
            split_bf(v.z, hz, lz); split_bf(v.w, hw, lw);
            int w0 = (G1_SA_H >> 2) + r * (ROWB >> 2) + 2 * k4;
            sw[w0]     = pack_bf2(hx, hy);
            sw[w0 + 1] = pack_bf2(hz, hw);
            int w1 = (G1_SA_L >> 2) + r * (ROWB >> 2) + 2 * k4;
            sw[w1]     = pack_bf2(lx, ly);
            sw[w1 + 1] = pack_bf2(lz, lw);
        }
    };
    auto cpB = [&](uint32_t bufbase, int kc) {
#pragma unroll
        for (int i = 0; i < 4; i++) {
            int idx = tid + i * 256; int n = idx >> 3, c = idx & 7;
            cp16(sbase + bufbase + G1_SB_H + (uint32_t)(n * ROWB + c * 16),
                 g_WkHi + (size_t)n * HD + kc + c * 8);
            cp16(sbase + bufbase + G1_SB_L + (uint32_t)(n * ROWB + c * 16),
                 g_WkLo + (size_t)n * HD + kc + c * 8);
        }
        asm volatile("cp.async.commit_group;" ::: "memory");
    };

    ldgA(0);
    stsA(0);
    cpB(0, 0);

    for (int it = 0; it < 8; ++it) {
        const uint32_t buf  = (uint32_t)(it & 1) * G1_STAGE;
        const uint32_t nbuf = (uint32_t)((it & 1) ^ 1) * G1_STAGE;

        __syncthreads();
        if (it < 7) {
            ldgA((it + 1) * 64);
            cpB(nbuf, (it + 1) * 64);
            asm volatile("cp.async.wait_group 1;" ::: "memory");
        } else {
            asm volatile("cp.async.wait_group 0;" ::: "memory");
        }
        __syncthreads();

        const uint32_t aBH = sbase + buf + aOffH;
        const uint32_t aBL = sbase + buf + aOffL;
        const uint32_t bBH = sbase + buf + bOffH;
        const uint32_t bBL = sbase + buf + bOffL;
#pragma unroll
        for (int ks = 0; ks < 4; ks++) {
            const uint32_t koff = ks * 32;
            uint32_t ah[2][4], al[2][4];
#pragma unroll
            for (int mt = 0; mt < 2; mt++) {
                ldsm4(aBH + (uint32_t)mt * 16 * ROWB + koff, ah[mt]);
                ldsm4(aBL + (uint32_t)mt * 16 * ROWB + koff, al[mt]);
            }
#pragma unroll
            for (int ng = 0; ng < 2; ng++) {
                uint32_t bh[4], bl[4];
                ldsm4(bBH + (uint32_t)ng * 16 * ROWB + koff, bh);
                ldsm4(bBL + (uint32_t)ng * 16 * ROWB + koff, bl);
#pragma unroll
                for (int mt = 0; mt < 2; mt++) {
                    mma16816(acc[mt][2 * ng],     ah[mt], bh[0], bh[2]);
                    mma16816(acc[mt][2 * ng],     ah[mt], bl[0], bl[2]);
                    mma16816(acc[mt][2 * ng],     al[mt], bh[0], bh[2]);
                    mma16816(acc[mt][2 * ng + 1], ah[mt], bh[1], bh[3]);
                    mma16816(acc[mt][2 * ng + 1], ah[mt], bl[1], bl[3]);
                    mma16816(acc[mt][2 * ng + 1], al[mt], bh[1], bh[3]);
                }
            }
        }

        if (it < 7) stsA(nbuf);
    }

    // epilogue: split fp32 acc -> K hi/lo bf16
#pragma unroll
    for (int mt = 0; mt < 2; mt++) {
        const int row0 = m0 + wm * 32 + mt * 16 + gid;
#pragma unroll
        for (int nt = 0; nt < 4; nt++) {
            const int col = wn * 32 + nt * 8 + tig * 2;
            __nv_bfloat16 h0, l0, h1, l1, h2, l2, h3, l3;
            split_bf(acc[mt][nt][0], h0, l0); split_bf(acc[mt][nt][1], h1, l1);
            split_bf(acc[mt][nt][2], h2, l2); split_bf(acc[mt][nt][3], h3, l3);
            *reinterpret_cast<uint32_t*>(g_Khi + (size_t)row0 * ID + col)       = pack_bf2(h0, h1);
            *reinterpret_cast<uint32_t*>(g_Klo + (size_t)row0 * ID + col)       = pack_bf2(l0, l1);
            *reinterpret_cast<uint32_t*>(g_Khi + (size_t)(row0 + 8) * ID + col) = pack_bf2(h2, h3);
            *reinterpret_cast<uint32_t*>(g_Klo + (size_t)(row0 + 8) * ID + col) = pack_bf2(l2, l3);
        }
    }
}

// ======================= G2: M[8192,256] = K[8192,128] @ (SCALE*WqT)^T (bf16 3-term) ===========
#define G2_SA_H 0
#define G2_SA_L (G2_SA_H + 64 * ROWB)
#define G2_SB_H (G2_SA_L + 64 * ROWB)
#define G2_SB_L (G2_SB_H + 256 * ROWB)
#define G2_STAGE (G2_SB_L + 256 * ROWB)     // 92160
#define G2_SMEM (2 * G2_STAGE)              // 184320

__global__ __launch_bounds__(256)
void gemm2_kernel()
{
    extern __shared__ char smem[];
    const uint32_t sbase = smem_u32(smem);

    const int tid  = threadIdx.x;
    const int lane = tid & 31;
    const int wid  = tid >> 5;
    const int wm   = wid & 1;
    const int wn   = wid >> 1;
    const int m0   = blockIdx.x * 64;
    const int gid  = lane >> 2;
    const int tig  = lane & 3;

    const uint32_t laneoff = (uint32_t)((lane & 15) * ROWB + (lane >> 4) * 16);
    const uint32_t aOffH = G2_SA_H + (uint32_t)(wm * 32) * ROWB + laneoff;
    const uint32_t aOffL = G2_SA_L + (uint32_t)(wm * 32) * ROWB + laneoff;
    const uint32_t bOffH = G2_SB_H + (uint32_t)(wn * 64) * ROWB + laneoff;
    const uint32_t bOffL = G2_SB_L + (uint32_t)(wn * 64) * ROWB + laneoff;

    float acc[2][8][4];
#pragma unroll
    for (int mt = 0; mt < 2; mt++)
#pragma unroll
        for (int nt = 0; nt < 8; nt++)
#pragma unroll
            for (int q = 0; q < 4; q++) acc[mt][nt][q] = 0.f;

    auto cpStage = [&](uint32_t bufbase, int kc) {
#pragma unroll
        for (int i = 0; i < 2; i++) {
            int idx = tid + i * 256; int n = idx >> 3, c = idx & 7;
            cp16(sbase + bufbase + G2_SA_H + (uint32_t)(n * ROWB + c * 16),
                 g_Khi + (size_t)(m0 + n) * ID + kc + c * 8);
            cp16(sbase + bufbase + G2_SA_L + (uint32_t)(n * ROWB + c * 16),
                 g_Klo + (size_t)(m0 + n) * ID + kc + c * 8);
        }
#pragma unroll
        for (int i = 0; i < 8; i++) {
            int idx = tid + i * 256; int n = idx >> 3, c = idx & 7;
            cp16(sbase + bufbase + G2_SB_H + (uint32_t)(n * ROWB + c * 16),
                 g_WqTHi + (size_t)n * ID + kc + c * 8);
            cp16(sbase + bufbase + G2_SB_L + (uint32_t)(n * ROWB + c * 16),
                 g_WqTLo + (size_t)n * ID + kc + c * 8);
        }
        asm volatile("cp.async.commit_group;" ::: "memory");
    };

    auto compute = [&](uint32_t buf) {
        const uint32_t aBH = sbase + buf + aOffH;
        const uint32_t aBL = sbase + buf + aOffL;
        const uint32_t bBH = sbase + buf + bOffH;
        const uint32_t bBL = sbase + buf + bOffL;
#pragma unroll
        for (int ks = 0; ks < 4; ks++) {
            const uint32_t koff = ks * 32;
            uint32_t ah[2][4], al[2][4];
#pragma unroll
            for (int mt = 0; mt < 2; mt++) {
                ldsm4(aBH + (uint32_t)mt * 16 * ROWB + koff, ah[mt]);
                ldsm4(aBL + (uint32_t)mt * 16 * ROWB + koff, al[mt]);
            }
#pragma unroll
            for (int ng = 0; ng < 4; ng++) {
                uint32_t bh[4], bl[4];
                ldsm4(bBH + (uint32_t)ng * 16 * ROWB + koff, bh);
                ldsm4(bBL + (uint32_t)ng * 16 * ROWB + koff, bl);
#pragma unroll
                for (int mt = 0; mt < 2; mt++) {
                    mma16816(acc[mt][2 * ng],     ah[mt], bh[0], bh[2]);
                    mma16816(acc[mt][2 * ng],     ah[mt], bl[0], bl[2]);
                    mma16816(acc[mt][2 * ng],     al[mt], bh[0], bh[2]);
                    mma16816(acc[mt][2 * ng + 1], ah[mt], bh[1], bh[3]);
                    mma16816(acc[mt][2 * ng + 1], ah[mt], bl[1], bl[3]);
                    mma16816(acc[mt][2 * ng + 1], al[mt], bh[1], bh[3]);
                }
            }
        }
    };

    cpStage(0, 0);
    cpStage(G2_STAGE, 64);
    asm volatile("cp.async.wait_group 1;" ::: "memory");
    __syncthreads();
    compute(0);
    asm volatile("cp.async.wait_group 0;" ::: "memory");
    __syncthreads();
    compute(G2_STAGE);

#pragma unroll
    for (int mt = 0; mt < 2; mt++) {
        const int row0 = m0 + wm * 32 + mt * 16 + gid;
#pragma unroll
        for (int nt = 0; nt < 8; nt++) {
            const int col = wn * 64 + nt * 8 + tig * 2;
            float2 v0 = make_float2(acc[mt][nt][0], acc[mt][nt][1]);
            float2 v1 = make_float2(acc[mt][nt][2], acc[mt][nt][3]);
            *reinterpret_cast<float2*>(g_M + (size_t)row0 * GD + col)       = v0;
            *reinterpret_cast<float2*>(g_M + (size_t)(row0 + 8) * GD + col) = v1;
        }
    }
}

// ======================= Kernel B: sim + masked softmax (R3/R6 proven form) ====================
#define JB2 8

__global__ __launch_bounds__(256)
void cal_sim_stream_kernel(const float* __restrict__ chg,          // [B, N, GD]
                           const unsigned int* __restrict__ maskw, // [B, N] dtype probed
                           float* __restrict__ out)                // [N, B]
{
    __shared__ float s_M[JB2 * GD];
    __shared__ float s_sim[BB * 9];

    const int t    = threadIdx.x;
    const int lane = t & 31;
    const int warp = t >> 5;
    const int j0   = blockIdx.x * JB2;

#pragma unroll
    for (int i = 0; i < 2; i++) {
        int idx = t + i * 256;
        *reinterpret_cast<float4*>(s_M + 4 * idx) =
            *reinterpret_cast<const float4*>(g_M + (size_t)j0 * GD + 4 * idx);
    }
    __syncthreads();

    float4 m0 = reinterpret_cast<const float4*>(s_M + warp * GD)[2 * lane];
    float4 m1 = reinterpret_cast<const float4*>(s_M + warp * GD)[2 * lane + 1];

    const float* crow = chg + (size_t)(j0 + warp) * GD;

#pragma unroll 8
    for (int b = 0; b < BB; b++) {
        const float4* c = reinterpret_cast<const float4*>(crow + (size_t)b * NTOK * GD);
        float4 c0 = c[2 * lane];
        float4 c1 = c[2 * lane + 1];
        float part = c0.x * m0.x + c0.y * m0.y + c0.z * m0.z + c0.w * m0.w
                   + c1.x * m1.x + c1.y * m1.y + c1.z * m1.z + c1.w * m1.w;
#pragma unroll
        for (int s = 16; s; s >>= 1) part += __shfl_xor_sync(0xffffffffu, part, s);
        if (lane == 0) s_sim[b * 9 + warp] = part;
    }
    __syncthreads();

    bool notint = false, notfloat = false;
    for (int i = lane; i < 256; i += 32) {
        unsigned int w = maskw[i];
        notint   |= (w > 1u);
        notfloat |= (w != 0u && w != 0x3f800000u);
    }
    notint   = __any_sync(0xffffffffu, notint);
    notfloat = __any_sync(0xffffffffu, notfloat);
    const int mode = notint ? (notfloat ? 1 : 2) : 0;   // 0=int32, 1=byte, 2=float32

    {
        const int jg = j0 + warp;
        float v = s_sim[lane * 9 + warp];
        bool mk;
        if (mode == 0)      mk = reinterpret_cast<const int*>(maskw)[(size_t)lane * NTOK + jg] != 0;
        else if (mode == 1) mk = reinterpret_cast<const unsigned char*>(maskw)[(size_t)lane * NTOK + jg] != 0;
        else                mk = reinterpret_cast<const float*>(maskw)[(size_t)lane * NTOK + jg] != 0.0f;
        v = mk ? v : -1e9f;
        float mx = v;
#pragma unroll
        for (int s = 16; s; s >>= 1) mx = fmaxf(mx, __shfl_xor_sync(0xffffffffu, mx, s));
        float ev = expf(v - mx);
        float sum = ev;
#pragma unroll
        for (int s = 16; s; s >>= 1) sum += __shfl_xor_sync(0xffffffffu, sum, s);
        out[(size_t)jg * BB + lane] = ev / sum;
    }
}

extern "C" void kernel_launch(void* const* d_in, const int* in_sizes, int n_in,
                              void* d_out, int out_size)
{
    const float*        chg  = (const float*)d_in[0];        // change_embeddings [B,N,256]
    const float*        edg  = (const float*)d_in[1];        // edges_embeddings  [N,512]
    const unsigned int* mask = (const unsigned int*)d_in[2]; // mask [B,N]
    const float*        Wq   = (const float*)d_in[3];        // [128,256]
    const float*        Wk   = (const float*)d_in[4];        // [128,512]
    float*              out  = (float*)d_out;                // [N,B]

    cudaFuncSetAttribute(gemm1_kernel,
                         cudaFuncAttributeMaxDynamicSharedMemorySize, G1_SMEM);
    cudaFuncSetAttribute(gemm2_kernel,
                         cudaFuncAttributeMaxDynamicSharedMemorySize, G2_SMEM);

    prep_split_kernel<<<48, 256>>>(Wq, Wk);
    gemm1_kernel<<<NTOK / 64, 256, G1_SMEM>>>(edg);
    gemm2_kernel<<<NTOK / 64, 256, G2_SMEM>>>();
    cal_sim_stream_kernel<<<NTOK / JB2, 256>>>(chg, mask, out);
}